// round 12
// baseline (speedup 1.0000x reference)
#include <cuda_runtime.h>
#include <cuda_fp16.h>
#include <math.h>
#include <stdint.h>

#define T_TOK 2048
#define D_HID 2048
#define N_INT 1024
#define N_EXP 8
#define N_SLOT (T_TOK*2)
#define NTILE_MAX 40            // sum ceil(cnt_e/128) <= 40

// ---------------- scratch ----------------
__device__ __align__(256) __half g_xh[(size_t)T_TOK * D_HID];
__device__ __align__(256) __half g_h[(size_t)N_SLOT * N_INT];
__device__ int   g_counts[N_EXP];
__device__ int   g_offsets[N_EXP];
__device__ int   g_tk_e[N_SLOT];
__device__ float g_tk_w[N_SLOT];
__device__ int   g_slot_tok2[N_SLOT];
__device__ float g_slot_w[N_SLOT];
__device__ int   g_tmap[NTILE_MAX];

// ---------------- helpers ----------------
__device__ __forceinline__ float gelu_exact(float v) {
    return 0.5f * v * (1.0f + erff(v * 0.70710678118654752f));
}
__device__ __forceinline__ uint32_t pack_h2(float lo, float hi) {
    uint32_t r; asm("cvt.rn.f16x2.f32 %0, %1, %2;" : "=r"(r) : "f"(hi), "f"(lo)); return r;
}
__device__ __forceinline__ uint2 pack_f4(float4 v) {
    return make_uint2(pack_h2(v.x, v.y), pack_h2(v.z, v.w));
}
__device__ __forceinline__ uint32_t smem_u32(const void* p) {
    uint32_t a;
    asm("{ .reg .u64 t; cvta.to.shared.u64 t, %1; cvt.u32.u64 %0, t; }" : "=r"(a) : "l"(p));
    return a;
}
__device__ __forceinline__ void cp_async16(uint32_t smem_dst, const void* gmem_src) {
    asm volatile("cp.async.cg.shared.global [%0], [%1], 16;\n" :: "r"(smem_dst), "l"(gmem_src));
}
__device__ __forceinline__ void cp_commit() { asm volatile("cp.async.commit_group;\n" ::: "memory"); }
template<int N>
__device__ __forceinline__ void cp_wait() { asm volatile("cp.async.wait_group %0;\n" :: "n"(N) : "memory"); }

__device__ __forceinline__ void ldsm_x4(uint32_t r[4], uint32_t addr) {
    asm volatile("ldmatrix.sync.aligned.m8n8.x4.shared.b16 {%0,%1,%2,%3}, [%4];"
                 : "=r"(r[0]), "=r"(r[1]), "=r"(r[2]), "=r"(r[3]) : "r"(addr));
}
__device__ __forceinline__ void ldsm_x4_t(uint32_t r[4], uint32_t addr) {
    asm volatile("ldmatrix.sync.aligned.m8n8.x4.trans.shared.b16 {%0,%1,%2,%3}, [%4];"
                 : "=r"(r[0]), "=r"(r[1]), "=r"(r[2]), "=r"(r[3]) : "r"(addr));
}
__device__ __forceinline__ void mma_f16(float c[4], const uint32_t a[4], const uint32_t b[2]) {
    asm volatile(
        "mma.sync.aligned.m16n8k16.row.col.f32.f16.f16.f32 "
        "{%0,%1,%2,%3}, {%4,%5,%6,%7}, {%8,%9}, {%0,%1,%2,%3};"
        : "+f"(c[0]), "+f"(c[1]), "+f"(c[2]), "+f"(c[3])
        : "r"(a[0]), "r"(a[1]), "r"(a[2]), "r"(a[3]), "r"(b[0]), "r"(b[1]));
}

// ---------------- router (+ fp16 conversion of x) ----------------
__global__ void router_kernel(const float* __restrict__ x, const float* __restrict__ gw,
                              const float* __restrict__ gb, float* __restrict__ logits_out) {
    int t = blockIdx.x, warp = threadIdx.x >> 5, lane = threadIdx.x & 31;
    const float* xr = x + (size_t)t * D_HID;
    float s = 0.0f;
    for (int i = lane; i < D_HID; i += 32) s += xr[i] * gw[i * N_EXP + warp];
#pragma unroll
    for (int o = 16; o; o >>= 1) s += __shfl_xor_sync(0xffffffffu, s, o);
    __shared__ float lg[N_EXP];
    if (lane == 0) lg[warp] = s + gb[warp];

    {
        const float4* x4 = (const float4*)xr;
        uint2* dst = (uint2*)(g_xh + (size_t)t * D_HID);
#pragma unroll
        for (int j = 0; j < 2; j++) {
            int i = threadIdx.x + j * 256;
            dst[i] = pack_f4(x4[i]);
        }
    }
    __syncthreads();

    if (threadIdx.x == 0) {
        float v0 = -1e30f, v1 = -1e30f; int e0 = 0, e1 = 0;
#pragma unroll
        for (int e = 0; e < N_EXP; e++) {
            float v = lg[e];
            logits_out[(size_t)t * N_EXP + e] = v;
            if (v > v0)      { v1 = v0; e1 = e0; v0 = v; e0 = e; }
            else if (v > v1) { v1 = v;  e1 = e; }
        }
        float d = expf(v1 - v0), w1 = d / (1.0f + d), w0 = 1.0f - w1;
        g_tk_e[2*t] = e0;   g_tk_w[2*t] = w0;
        g_tk_e[2*t+1] = e1; g_tk_w[2*t+1] = w1;
    }
}

// ---------------- fused histogram + offsets + scatter + tile map ----------------
__global__ void scatter_kernel() {
    __shared__ int cnt[N_EXP], offs[N_EXP], cur[N_EXP];
    int tid = threadIdx.x;
    if (tid < N_EXP) cnt[tid] = 0;
    __syncthreads();
    int myE[4];
#pragma unroll
    for (int j = 0; j < 4; j++) {
        int i = tid + j * 1024;
        myE[j] = g_tk_e[i];
        atomicAdd(&cnt[myE[j]], 1);
    }
    __syncthreads();
    if (tid == 0) {
        int run = 0, nt = 0;
#pragma unroll
        for (int e = 0; e < N_EXP; e++) {
            offs[e] = run; cur[e] = run; run += cnt[e];
            int mt = (cnt[e] + 127) >> 7;
            for (int m = 0; m < mt; m++) g_tmap[nt++] = (e << 16) | m;
        }
        for (; nt < NTILE_MAX; nt++) g_tmap[nt] = -1;
    }
    __syncthreads();
#pragma unroll
    for (int j = 0; j < 4; j++) {
        int i = tid + j * 1024;
        int pos = atomicAdd(&cur[myE[j]], 1);
        g_slot_tok2[pos] = i;
        g_slot_w[pos]    = g_tk_w[i];
    }
    if (tid < N_EXP) { g_counts[tid] = cnt[tid]; g_offsets[tid] = offs[tid]; }
}

// ---------------- GEMM config: BK=32, 3 stages, 128 threads, warp 64-wide-M ----------------
#define STAGES 3
#define A_ROW  80
#define A_SZ   (128 * A_ROW)    // 10240

extern __shared__ char smem_c[];

// =======================================================================
// GEMM1: 128x64x32 dual-B. 4 warps 2x2; warp tile 64x32 per matrix.
//   32 MMA per 8 ldsm per ks (4.0 mma/ldsm)
// =======================================================================
#define B1_ROW 144
#define B1_SZ  (32 * B1_ROW)
#define G1_STG (A_SZ + 2 * B1_SZ)
#define G1_SMEM (STAGES * G1_STG)

__global__ void __launch_bounds__(128, 2)
gemm1_kernel(const float* __restrict__ w_up, const float* __restrict__ w_gate) {
    int tmv = g_tmap[blockIdx.y];
    if (tmv < 0) return;
    int e = tmv >> 16, m0 = (tmv & 0xffff) * 128;
    int cnt = g_counts[e];
    int n0 = blockIdx.x * 64;
    int off = g_offsets[e];
    const float* Wu = w_up   + (size_t)e * D_HID * N_INT;
    const float* Wg = w_gate + (size_t)e * D_HID * N_INT;

    char* smem = smem_c;
    uint32_t sbase = smem_u32(smem_c);

    int tid = threadIdx.x;
    int warp = tid >> 5, lane = tid & 31;
    int wm = warp >> 1, wn = warp & 1;
    int grp = lane >> 2, qid = lane & 3;

    // A producer: one row per thread (128 rows), 4 chunks of 16B
    int gmA = m0 + tid;
    int slotA = (gmA < cnt) ? (off + gmA) : off;
    const __half* aptr = g_xh + (size_t)(g_slot_tok2[slotA] >> 1) * D_HID;

    // B producer: row = tid>>2 (0..31), seg = tid&3 (16 floats each)
    int kB = tid >> 2, segB = tid & 3;
    const float* pu = Wu + (size_t)kB * N_INT + n0 + segB * 16;
    const float* pg = Wg + (size_t)kB * N_INT + n0 + segB * 16;
    uint32_t bso = kB * B1_ROW + segB * 32;

    int lr = lane & 7, ls = lane >> 3;
    uint32_t aOff = (wm*64 + (ls & 1)*8 + lr) * A_ROW + (ls >> 1) * 16;
    uint32_t bOff = ((ls & 1)*8 + lr) * B1_ROW + wn*64 + (ls >> 1)*16;

    float accU[4][4][4], accG[4][4][4];
#pragma unroll
    for (int a = 0; a < 4; a++)
#pragma unroll
        for (int b = 0; b < 4; b++)
#pragma unroll
            for (int c = 0; c < 4; c++) { accU[a][b][c] = 0.f; accG[a][b][c] = 0.f; }

    const int KT = D_HID / 32;   // 64
    float4 rbu[4], rbg[4];

    auto prefetchB = [&](int kt) {
        size_t ko = (size_t)kt * 32 * N_INT;
#pragma unroll
        for (int i = 0; i < 4; i++) {
            rbu[i] = *(const float4*)(pu + ko + i * 4);
            rbg[i] = *(const float4*)(pg + ko + i * 4);
        }
    };
    auto fill = [&](int kt) {
        int s = kt % STAGES;
        char* sb = smem + s*G1_STG + A_SZ;
#pragma unroll
        for (int i = 0; i < 4; i++) {
            *(uint2*)(sb + bso + i * 8)         = pack_f4(rbu[i]);
            *(uint2*)(sb + B1_SZ + bso + i * 8) = pack_f4(rbg[i]);
        }
        uint32_t sa = sbase + s*G1_STG + tid * A_ROW;
#pragma unroll
        for (int c = 0; c < 4; c++)
            cp_async16(sa + c*16, aptr + kt*32 + c*8);
        cp_commit();
    };

    prefetchB(0); fill(0);
    prefetchB(1); fill(1);
    prefetchB(2);

    for (int kt = 0; kt < KT; kt++) {
        cp_wait<1>();
        __syncthreads();

        if (kt + 2 < KT) {
            fill(kt + 2);
            if (kt + 3 < KT) prefetchB(kt + 3);
        } else cp_commit();

        int s = kt % STAGES;
        uint32_t aB = sbase + s*G1_STG + aOff;
        uint32_t bB = sbase + s*G1_STG + A_SZ + bOff;
#pragma unroll
        for (int ks = 0; ks < 2; ks++) {
            uint32_t a[4][4];
#pragma unroll
            for (int fm = 0; fm < 4; fm++) ldsm_x4(a[fm], aB + fm*(16*A_ROW) + ks*32);
            uint32_t bu[2][4], bg[2][4];
#pragma unroll
            for (int p = 0; p < 2; p++) {
                ldsm_x4_t(bu[p], bB + p*32 + ks*(16*B1_ROW));
                ldsm_x4_t(bg[p], bB + B1_SZ + p*32 + ks*(16*B1_ROW));
            }
#pragma unroll
            for (int fm = 0; fm < 4; fm++)
#pragma unroll
                for (int p = 0; p < 2; p++) {
                    mma_f16(accU[fm][2*p],   a[fm], &bu[p][0]);
                    mma_f16(accU[fm][2*p+1], a[fm], &bu[p][2]);
                    mma_f16(accG[fm][2*p],   a[fm], &bg[p][0]);
                    mma_f16(accG[fm][2*p+1], a[fm], &bg[p][2]);
                }
        }
    }

#pragma unroll
    for (int fm = 0; fm < 4; fm++) {
        int r0 = wm*64 + fm*16 + grp;
#pragma unroll
        for (int half_ = 0; half_ < 2; half_++) {
            int gm = m0 + r0 + half_*8;
            if (gm < cnt) {
                __half* hrow = g_h + (size_t)(off + gm) * N_INT + n0;
#pragma unroll
                for (int fn = 0; fn < 4; fn++) {
                    int c = wn*32 + fn*8 + qid*2;
                    float u0 = accU[fm][fn][half_*2+0], u1 = accU[fm][fn][half_*2+1];
                    float g0 = accG[fm][fn][half_*2+0], g1 = accG[fm][fn][half_*2+1];
                    float h0 = gelu_exact(u0) * (g0 + 1.0f);
                    float h1 = gelu_exact(u1) * (g1 + 1.0f);
                    *(uint32_t*)(hrow + c) = pack_h2(h0, h1);
                }
            }
        }
    }
}

// =======================================================================
// GEMM2: 128x128x32. 4 warps 2x2; warp tile 64x64. out += w * (h @ Wd)
// =======================================================================
#define B2_ROW 272
#define B2_SZ  (32 * B2_ROW)
#define G2_STG (A_SZ + B2_SZ)
#define G2_SMEM (STAGES * G2_STG)

__global__ void __launch_bounds__(128, 2)
gemm2_kernel(const float* __restrict__ w_down, float* __restrict__ out) {
    int tmv = g_tmap[blockIdx.y];
    if (tmv < 0) return;
    int e = tmv >> 16, m0 = (tmv & 0xffff) * 128;
    int cnt = g_counts[e];
    int n0 = blockIdx.x * 128;
    int off = g_offsets[e];
    const float* Wd = w_down + (size_t)e * N_INT * D_HID;

    char* smem = smem_c;
    uint32_t sbase = smem_u32(smem_c);

    int tid = threadIdx.x;
    int warp = tid >> 5, lane = tid & 31;
    int wm = warp >> 1, wn = warp & 1;
    int grp = lane >> 2, qid = lane & 3;

    int gmA = m0 + tid;
    int slotA = (gmA < cnt) ? (off + gmA) : off;
    const __half* aptr = g_h + (size_t)slotA * N_INT;

    // B: row = tid>>2 (0..31), seg = tid&3 (32 floats each)
    int kB = tid >> 2, segB = tid & 3;
    const float* pd = Wd + (size_t)kB * D_HID + n0 + segB * 32;
    uint32_t bso = kB * B2_ROW + segB * 64;

    int lr = lane & 7, ls = lane >> 3;
    uint32_t aOff = (wm*64 + (ls & 1)*8 + lr) * A_ROW + (ls >> 1) * 16;
    uint32_t bOff = ((ls & 1)*8 + lr) * B2_ROW + wn*128 + (ls >> 1)*16;

    float acc[4][8][4];
#pragma unroll
    for (int a = 0; a < 4; a++)
#pragma unroll
        for (int b = 0; b < 8; b++)
#pragma unroll
            for (int c = 0; c < 4; c++) acc[a][b][c] = 0.f;

    const int KT = N_INT / 32;   // 32
    float4 rb[8];

    auto prefetchB = [&](int kt) {
        size_t ko = (size_t)kt * 32 * D_HID;
#pragma unroll
        for (int i = 0; i < 8; i++)
            rb[i] = *(const float4*)(pd + ko + i * 4);
    };
    auto fill = [&](int kt) {
        int s = kt % STAGES;
        char* sb = smem + s*G2_STG + A_SZ;
#pragma unroll
        for (int i = 0; i < 8; i++)
            *(uint2*)(sb + bso + i * 8) = pack_f4(rb[i]);
        uint32_t sa = sbase + s*G2_STG + tid * A_ROW;
#pragma unroll
        for (int c = 0; c < 4; c++)
            cp_async16(sa + c*16, aptr + kt*32 + c*8);
        cp_commit();
    };

    prefetchB(0); fill(0);
    prefetchB(1); fill(1);
    prefetchB(2);

    for (int kt = 0; kt < KT; kt++) {
        cp_wait<1>();
        __syncthreads();

        if (kt + 2 < KT) {
            fill(kt + 2);
            if (kt + 3 < KT) prefetchB(kt + 3);
        } else cp_commit();

        int s = kt % STAGES;
        uint32_t aB = sbase + s*G2_STG + aOff;
        uint32_t bB = sbase + s*G2_STG + A_SZ + bOff;
#pragma unroll
        for (int ks = 0; ks < 2; ks++) {
            uint32_t a[4][4];
#pragma unroll
            for (int fm = 0; fm < 4; fm++) ldsm_x4(a[fm], aB + fm*(16*A_ROW) + ks*32);
            uint32_t b[4][4];
#pragma unroll
            for (int p = 0; p < 4; p++)
                ldsm_x4_t(b[p], bB + p*32 + ks*(16*B2_ROW));
#pragma unroll
            for (int fm = 0; fm < 4; fm++)
#pragma unroll
                for (int p = 0; p < 4; p++) {
                    mma_f16(acc[fm][2*p],   a[fm], &b[p][0]);
                    mma_f16(acc[fm][2*p+1], a[fm], &b[p][2]);
                }
        }
    }

    // epilogue: out[tok] += w * acc (exactly 2 adds/element -> deterministic)
#pragma unroll
    for (int fm = 0; fm < 4; fm++) {
        int r0 = wm*64 + fm*16 + grp;
#pragma unroll
        for (int half_ = 0; half_ < 2; half_++) {
            int gm = m0 + r0 + half_*8;
            if (gm < cnt) {
                int slot = off + gm;
                int tok = g_slot_tok2[slot] >> 1;
                float wv = g_slot_w[slot];
                float* orow = out + (size_t)tok * D_HID + n0;
#pragma unroll
                for (int fn = 0; fn < 8; fn++) {
                    int c = wn*64 + fn*8 + qid*2;
                    atomicAdd(orow + c,     wv * acc[fm][fn][half_*2+0]);
                    atomicAdd(orow + c + 1, wv * acc[fm][fn][half_*2+1]);
                }
            }
        }
    }
}

// ---------------- launch ----------------
extern "C" void kernel_launch(void* const* d_in, const int* in_sizes, int n_in,
                              void* d_out, int out_size) {
    const float* x  = (const float*)d_in[0];
    const float* gw = (const float*)d_in[1];
    const float* gb = (const float*)d_in[2];
    const float* wu = (const float*)d_in[3];
    const float* wg = (const float*)d_in[4];
    const float* wd = (const float*)d_in[5];

    float* out    = (float*)d_out;
    float* logits = out + (out_size - T_TOK * N_EXP);

    cudaFuncSetAttribute(gemm1_kernel, cudaFuncAttributeMaxDynamicSharedMemorySize, G1_SMEM);
    cudaFuncSetAttribute(gemm2_kernel, cudaFuncAttributeMaxDynamicSharedMemorySize, G2_SMEM);

    cudaMemsetAsync(out, 0, (size_t)T_TOK * D_HID * sizeof(float));
    router_kernel<<<T_TOK, 256>>>(x, gw, gb, logits);
    scatter_kernel<<<1, 1024>>>();

    dim3 g1(N_INT / 64, NTILE_MAX, 1);     // (16, 40)
    gemm1_kernel<<<g1, 128, G1_SMEM>>>(wu, wg);

    dim3 g2(D_HID / 128, NTILE_MAX, 1);    // (16, 40)
    gemm2_kernel<<<g2, 128, G2_SMEM>>>(wd, out);
}

// round 13
// speedup vs baseline: 1.1309x; 1.1309x over previous
#include <cuda_runtime.h>
#include <cuda_fp16.h>
#include <math.h>
#include <stdint.h>

#define T_TOK 2048
#define D_HID 2048
#define N_INT 1024
#define N_EXP 8
#define N_SLOT (T_TOK*2)
#define NTILE_MAX 72            // tiles of 64 rows: <= 4096/64 + 8

// ---------------- scratch ----------------
__device__ __align__(256) __half g_xh[(size_t)T_TOK * D_HID];
__device__ __align__(256) __half g_h[(size_t)N_SLOT * N_INT];
__device__ int   g_counts[N_EXP];
__device__ int   g_offsets[N_EXP];
__device__ int   g_tk_e[N_SLOT];
__device__ float g_tk_w[N_SLOT];
__device__ int   g_slot_tok2[N_SLOT];
__device__ float g_slot_w[N_SLOT];
__device__ int   g_tmap[NTILE_MAX];

// ---------------- helpers ----------------
__device__ __forceinline__ float gelu_exact(float v) {
    return 0.5f * v * (1.0f + erff(v * 0.70710678118654752f));
}
__device__ __forceinline__ uint32_t pack_h2(float lo, float hi) {
    uint32_t r; asm("cvt.rn.f16x2.f32 %0, %1, %2;" : "=r"(r) : "f"(hi), "f"(lo)); return r;
}
__device__ __forceinline__ uint2 pack_f4(float4 v) {
    return make_uint2(pack_h2(v.x, v.y), pack_h2(v.z, v.w));
}
__device__ __forceinline__ uint32_t smem_u32(const void* p) {
    uint32_t a;
    asm("{ .reg .u64 t; cvta.to.shared.u64 t, %1; cvt.u32.u64 %0, t; }" : "=r"(a) : "l"(p));
    return a;
}
__device__ __forceinline__ void cp_async16(uint32_t smem_dst, const void* gmem_src) {
    asm volatile("cp.async.cg.shared.global [%0], [%1], 16;\n" :: "r"(smem_dst), "l"(gmem_src));
}
__device__ __forceinline__ void cp_commit() { asm volatile("cp.async.commit_group;\n" ::: "memory"); }
template<int N>
__device__ __forceinline__ void cp_wait() { asm volatile("cp.async.wait_group %0;\n" :: "n"(N) : "memory"); }

__device__ __forceinline__ void ldsm_x4(uint32_t r[4], uint32_t addr) {
    asm volatile("ldmatrix.sync.aligned.m8n8.x4.shared.b16 {%0,%1,%2,%3}, [%4];"
                 : "=r"(r[0]), "=r"(r[1]), "=r"(r[2]), "=r"(r[3]) : "r"(addr));
}
__device__ __forceinline__ void ldsm_x4_t(uint32_t r[4], uint32_t addr) {
    asm volatile("ldmatrix.sync.aligned.m8n8.x4.trans.shared.b16 {%0,%1,%2,%3}, [%4];"
                 : "=r"(r[0]), "=r"(r[1]), "=r"(r[2]), "=r"(r[3]) : "r"(addr));
}
__device__ __forceinline__ void mma_f16(float c[4], const uint32_t a[4], const uint32_t b[2]) {
    asm volatile(
        "mma.sync.aligned.m16n8k16.row.col.f32.f16.f16.f32 "
        "{%0,%1,%2,%3}, {%4,%5,%6,%7}, {%8,%9}, {%0,%1,%2,%3};"
        : "+f"(c[0]), "+f"(c[1]), "+f"(c[2]), "+f"(c[3])
        : "r"(a[0]), "r"(a[1]), "r"(a[2]), "r"(a[3]), "r"(b[0]), "r"(b[1]));
}

// ---------------- router (+ fp16 conversion of x) ----------------
__global__ void router_kernel(const float* __restrict__ x, const float* __restrict__ gw,
                              const float* __restrict__ gb, float* __restrict__ logits_out) {
    int t = blockIdx.x, warp = threadIdx.x >> 5, lane = threadIdx.x & 31;
    const float* xr = x + (size_t)t * D_HID;
    float s = 0.0f;
    for (int i = lane; i < D_HID; i += 32) s += xr[i] * gw[i * N_EXP + warp];
#pragma unroll
    for (int o = 16; o; o >>= 1) s += __shfl_xor_sync(0xffffffffu, s, o);
    __shared__ float lg[N_EXP];
    if (lane == 0) lg[warp] = s + gb[warp];

    {
        const float4* x4 = (const float4*)xr;
        uint2* dst = (uint2*)(g_xh + (size_t)t * D_HID);
#pragma unroll
        for (int j = 0; j < 2; j++) {
            int i = threadIdx.x + j * 256;
            dst[i] = pack_f4(x4[i]);
        }
    }
    __syncthreads();

    if (threadIdx.x == 0) {
        float v0 = -1e30f, v1 = -1e30f; int e0 = 0, e1 = 0;
#pragma unroll
        for (int e = 0; e < N_EXP; e++) {
            float v = lg[e];
            logits_out[(size_t)t * N_EXP + e] = v;
            if (v > v0)      { v1 = v0; e1 = e0; v0 = v; e0 = e; }
            else if (v > v1) { v1 = v;  e1 = e; }
        }
        float d = expf(v1 - v0), w1 = d / (1.0f + d), w0 = 1.0f - w1;
        g_tk_e[2*t] = e0;   g_tk_w[2*t] = w0;
        g_tk_e[2*t+1] = e1; g_tk_w[2*t+1] = w1;
    }
}

// ---------------- fused histogram + offsets + scatter + tile map ----------------
__global__ void scatter_kernel() {
    __shared__ int cnt[N_EXP], offs[N_EXP], cur[N_EXP];
    int tid = threadIdx.x;
    if (tid < N_EXP) cnt[tid] = 0;
    __syncthreads();
    int myE[4];
#pragma unroll
    for (int j = 0; j < 4; j++) {
        int i = tid + j * 1024;
        myE[j] = g_tk_e[i];
        atomicAdd(&cnt[myE[j]], 1);
    }
    __syncthreads();
    if (tid == 0) {
        int run = 0, nt = 0;
#pragma unroll
        for (int e = 0; e < N_EXP; e++) {
            offs[e] = run; cur[e] = run; run += cnt[e];
            int mt = (cnt[e] + 63) >> 6;        // tiles of 64 rows
            for (int m = 0; m < mt; m++) g_tmap[nt++] = (e << 16) | m;
        }
        for (; nt < NTILE_MAX; nt++) g_tmap[nt] = -1;
    }
    __syncthreads();
#pragma unroll
    for (int j = 0; j < 4; j++) {
        int i = tid + j * 1024;
        int pos = atomicAdd(&cur[myE[j]], 1);
        g_slot_tok2[pos] = i;
        g_slot_w[pos]    = g_tk_w[i];
    }
    if (tid < N_EXP) { g_counts[tid] = cnt[tid]; g_offsets[tid] = offs[tid]; }
}

// ---------------- GEMM config: BM=64, BK=32, 3 stages, 256 thr, 8 warps 2x4 ----------------
#define STAGES 3
#define A_ROW  80               // 64B data + 16B pad
#define A_SZ   (64 * A_ROW)     // 5120

extern __shared__ char smem_c[];

// =======================================================================
// GEMM1: 64x64x32 dual-B. 8 warps 2x4; warp tile 32x16 per matrix.
//   acc = 32 regs; target 3 CTAs/SM.
// =======================================================================
#define B1_ROW 144
#define B1_SZ  (32 * B1_ROW)        // 4608
#define G1_STG (A_SZ + 2 * B1_SZ)   // 14336
#define G1_SMEM (STAGES * G1_STG)   // 43008

__global__ void __launch_bounds__(256, 3)
gemm1_kernel(const float* __restrict__ w_up, const float* __restrict__ w_gate) {
    int tmv = g_tmap[blockIdx.y];
    if (tmv < 0) return;
    int e = tmv >> 16, m0 = (tmv & 0xffff) * 64;
    int cnt = g_counts[e];
    int n0 = blockIdx.x * 64;
    int off = g_offsets[e];
    const float* Wu = w_up   + (size_t)e * D_HID * N_INT;
    const float* Wg = w_gate + (size_t)e * D_HID * N_INT;

    char* smem = smem_c;
    uint32_t sbase = smem_u32(smem_c);

    int tid = threadIdx.x;
    int warp = tid >> 5, lane = tid & 31;
    int wm = warp >> 2, wn = warp & 3;       // 2x4
    int grp = lane >> 2, qid = lane & 3;

    // A producer: row = tid>>2 (0..63), chunk = tid&3 (16B)
    int rA = tid >> 2, qA = tid & 3;
    int gmA = m0 + rA;
    int slotA = (gmA < cnt) ? (off + gmA) : off;
    const __half* aptr = g_xh + (size_t)(g_slot_tok2[slotA] >> 1) * D_HID + qA * 8;

    // B producer: row = tid>>3 (0..31), seg = tid&7 (8 floats = 2 float4)
    int kB = tid >> 3, segB = tid & 7;
    const float* pu = Wu + (size_t)kB * N_INT + n0 + segB * 8;
    const float* pg = Wg + (size_t)kB * N_INT + n0 + segB * 8;
    uint32_t bso = kB * B1_ROW + segB * 16;

    int lr = lane & 7, ls = lane >> 3;
    uint32_t aOff = (wm*32 + (ls & 1)*8 + lr) * A_ROW + (ls >> 1) * 16;
    uint32_t bOff = ((ls & 1)*8 + lr) * B1_ROW + wn*32 + (ls >> 1) * 16;

    float accU[2][2][4], accG[2][2][4];
#pragma unroll
    for (int a = 0; a < 2; a++)
#pragma unroll
        for (int b = 0; b < 2; b++)
#pragma unroll
            for (int c = 0; c < 4; c++) { accU[a][b][c] = 0.f; accG[a][b][c] = 0.f; }

    const int KT = D_HID / 32;   // 64
    float4 rbu[2], rbg[2];

    auto prefetchB = [&](int kt) {
        size_t ko = (size_t)kt * 32 * N_INT;
        rbu[0] = *(const float4*)(pu + ko);     rbu[1] = *(const float4*)(pu + ko + 4);
        rbg[0] = *(const float4*)(pg + ko);     rbg[1] = *(const float4*)(pg + ko + 4);
    };
    auto fill = [&](int kt) {
        int s = kt % STAGES;
        char* sb = smem + s*G1_STG + A_SZ;
        *(uint2*)(sb + bso)             = pack_f4(rbu[0]);
        *(uint2*)(sb + bso + 8)         = pack_f4(rbu[1]);
        *(uint2*)(sb + B1_SZ + bso)     = pack_f4(rbg[0]);
        *(uint2*)(sb + B1_SZ + bso + 8) = pack_f4(rbg[1]);
        cp_async16(sbase + s*G1_STG + rA*A_ROW + qA*16, aptr + kt*32);
        cp_commit();
    };

    prefetchB(0); fill(0);
    prefetchB(1); fill(1);
    prefetchB(2);

    for (int kt = 0; kt < KT; kt++) {
        cp_wait<1>();
        __syncthreads();

        if (kt + 2 < KT) {
            fill(kt + 2);
            if (kt + 3 < KT) prefetchB(kt + 3);
        } else cp_commit();

        int s = kt % STAGES;
        uint32_t aB = sbase + s*G1_STG + aOff;
        uint32_t bB = sbase + s*G1_STG + A_SZ + bOff;
#pragma unroll
        for (int ks = 0; ks < 2; ks++) {
            uint32_t a[2][4];
#pragma unroll
            for (int fm = 0; fm < 2; fm++) ldsm_x4(a[fm], aB + fm*(16*A_ROW) + ks*32);
            uint32_t bu[4], bg[4];
            ldsm_x4_t(bu, bB + ks*(16*B1_ROW));
            ldsm_x4_t(bg, bB + B1_SZ + ks*(16*B1_ROW));
#pragma unroll
            for (int fm = 0; fm < 2; fm++) {
                mma_f16(accU[fm][0], a[fm], &bu[0]);
                mma_f16(accU[fm][1], a[fm], &bu[2]);
                mma_f16(accG[fm][0], a[fm], &bg[0]);
                mma_f16(accG[fm][1], a[fm], &bg[2]);
            }
        }
    }

    // epilogue: h = gelu(up)*(gate+1) -> g_h
#pragma unroll
    for (int fm = 0; fm < 2; fm++) {
        int r0 = wm*32 + fm*16 + grp;
#pragma unroll
        for (int half_ = 0; half_ < 2; half_++) {
            int gm = m0 + r0 + half_*8;
            if (gm < cnt) {
                __half* hrow = g_h + (size_t)(off + gm) * N_INT + n0;
#pragma unroll
                for (int fn = 0; fn < 2; fn++) {
                    int c = wn*16 + fn*8 + qid*2;
                    float u0 = accU[fm][fn][half_*2+0], u1 = accU[fm][fn][half_*2+1];
                    float g0 = accG[fm][fn][half_*2+0], g1 = accG[fm][fn][half_*2+1];
                    float h0 = gelu_exact(u0) * (g0 + 1.0f);
                    float h1 = gelu_exact(u1) * (g1 + 1.0f);
                    *(uint32_t*)(hrow + c) = pack_h2(h0, h1);
                }
            }
        }
    }
}

// =======================================================================
// GEMM2: 64x128x32. 8 warps 2x4; warp tile 32x32. out += w * (h @ Wd)
// =======================================================================
#define B2_ROW 272
#define B2_SZ  (32 * B2_ROW)        // 8704
#define G2_STG (A_SZ + B2_SZ)       // 13824
#define G2_SMEM (STAGES * G2_STG)   // 41472

__global__ void __launch_bounds__(256, 3)
gemm2_kernel(const float* __restrict__ w_down, float* __restrict__ out) {
    int tmv = g_tmap[blockIdx.y];
    if (tmv < 0) return;
    int e = tmv >> 16, m0 = (tmv & 0xffff) * 64;
    int cnt = g_counts[e];
    int n0 = blockIdx.x * 128;
    int off = g_offsets[e];
    const float* Wd = w_down + (size_t)e * N_INT * D_HID;

    char* smem = smem_c;
    uint32_t sbase = smem_u32(smem_c);

    int tid = threadIdx.x;
    int warp = tid >> 5, lane = tid & 31;
    int wm = warp >> 2, wn = warp & 3;       // 2x4
    int grp = lane >> 2, qid = lane & 3;

    int rA = tid >> 2, qA = tid & 3;
    int gmA = m0 + rA;
    int slotA = (gmA < cnt) ? (off + gmA) : off;
    const __half* aptr = g_h + (size_t)slotA * N_INT + qA * 8;

    // B producer: row = tid>>3 (0..31), seg = tid&7 (16 floats = 4 float4)
    int kB = tid >> 3, segB = tid & 7;
    const float* pd = Wd + (size_t)kB * D_HID + n0 + segB * 16;
    uint32_t bso = kB * B2_ROW + segB * 32;

    int lr = lane & 7, ls = lane >> 3;
    uint32_t aOff = (wm*32 + (ls & 1)*8 + lr) * A_ROW + (ls >> 1) * 16;
    uint32_t bOff = ((ls & 1)*8 + lr) * B2_ROW + wn*64 + (ls >> 1) * 16;

    float acc[2][4][4];
#pragma unroll
    for (int a = 0; a < 2; a++)
#pragma unroll
        for (int b = 0; b < 4; b++)
#pragma unroll
            for (int c = 0; c < 4; c++) acc[a][b][c] = 0.f;

    const int KT = N_INT / 32;   // 32
    float4 rb[4];

    auto prefetchB = [&](int kt) {
        size_t ko = (size_t)kt * 32 * D_HID;
#pragma unroll
        for (int i = 0; i < 4; i++)
            rb[i] = *(const float4*)(pd + ko + i * 4);
    };
    auto fill = [&](int kt) {
        int s = kt % STAGES;
        char* sb = smem + s*G2_STG + A_SZ;
#pragma unroll
        for (int i = 0; i < 4; i++)
            *(uint2*)(sb + bso + i * 8) = pack_f4(rb[i]);
        cp_async16(sbase + s*G2_STG + rA*A_ROW + qA*16, aptr + kt*32);
        cp_commit();
    };

    prefetchB(0); fill(0);
    prefetchB(1); fill(1);
    prefetchB(2);

    for (int kt = 0; kt < KT; kt++) {
        cp_wait<1>();
        __syncthreads();

        if (kt + 2 < KT) {
            fill(kt + 2);
            if (kt + 3 < KT) prefetchB(kt + 3);
        } else cp_commit();

        int s = kt % STAGES;
        uint32_t aB = sbase + s*G2_STG + aOff;
        uint32_t bB = sbase + s*G2_STG + A_SZ + bOff;
#pragma unroll
        for (int ks = 0; ks < 2; ks++) {
            uint32_t a[2][4];
#pragma unroll
            for (int fm = 0; fm < 2; fm++) ldsm_x4(a[fm], aB + fm*(16*A_ROW) + ks*32);
            uint32_t b[2][4];
#pragma unroll
            for (int p = 0; p < 2; p++)
                ldsm_x4_t(b[p], bB + p*32 + ks*(16*B2_ROW));
#pragma unroll
            for (int fm = 0; fm < 2; fm++)
#pragma unroll
                for (int p = 0; p < 2; p++) {
                    mma_f16(acc[fm][2*p],   a[fm], &b[p][0]);
                    mma_f16(acc[fm][2*p+1], a[fm], &b[p][2]);
                }
        }
    }

    // epilogue: out[tok] += w * acc (exactly 2 adds/element -> deterministic)
#pragma unroll
    for (int fm = 0; fm < 2; fm++) {
        int r0 = wm*32 + fm*16 + grp;
#pragma unroll
        for (int half_ = 0; half_ < 2; half_++) {
            int gm = m0 + r0 + half_*8;
            if (gm < cnt) {
                int slot = off + gm;
                int tok = g_slot_tok2[slot] >> 1;
                float wv = g_slot_w[slot];
                float* orow = out + (size_t)tok * D_HID + n0;
#pragma unroll
                for (int fn = 0; fn < 4; fn++) {
                    int c = wn*32 + fn*8 + qid*2;
                    atomicAdd(orow + c,     wv * acc[fm][fn][half_*2+0]);
                    atomicAdd(orow + c + 1, wv * acc[fm][fn][half_*2+1]);
                }
            }
        }
    }
}

// ---------------- launch ----------------
extern "C" void kernel_launch(void* const* d_in, const int* in_sizes, int n_in,
                              void* d_out, int out_size) {
    const float* x  = (const float*)d_in[0];
    const float* gw = (const float*)d_in[1];
    const float* gb = (const float*)d_in[2];
    const float* wu = (const float*)d_in[3];
    const float* wg = (const float*)d_in[4];
    const float* wd = (const float*)d_in[5];

    float* out    = (float*)d_out;
    float* logits = out + (out_size - T_TOK * N_EXP);

    cudaFuncSetAttribute(gemm1_kernel, cudaFuncAttributeMaxDynamicSharedMemorySize, G1_SMEM);
    cudaFuncSetAttribute(gemm2_kernel, cudaFuncAttributeMaxDynamicSharedMemorySize, G2_SMEM);

    cudaMemsetAsync(out, 0, (size_t)T_TOK * D_HID * sizeof(float));
    router_kernel<<<T_TOK, 256>>>(x, gw, gb, logits);
    scatter_kernel<<<1, 1024>>>();

    dim3 g1(N_INT / 64, NTILE_MAX, 1);     // (16, 72)
    gemm1_kernel<<<g1, 256, G1_SMEM>>>(wu, wg);

    dim3 g2(D_HID / 128, NTILE_MAX, 1);    // (16, 72)
    gemm2_kernel<<<g2, 256, G2_SMEM>>>(wd, out);
}

// round 14
// speedup vs baseline: 1.6767x; 1.4826x over previous
#include <cuda_runtime.h>
#include <cuda_fp16.h>
#include <math.h>
#include <stdint.h>

#define T_TOK 2048
#define D_HID 2048
#define N_INT 1024
#define N_EXP 8
#define N_SLOT (T_TOK*2)
#define NTILE_MAX 40            // sum ceil(cnt_e/128) <= 40

// ---------------- scratch ----------------
__device__ __align__(256) __half g_xh[(size_t)T_TOK * D_HID];   // fp16 x (router writes)
__device__ __align__(256) __half g_h[(size_t)N_SLOT * N_INT];   // fp16 intermediate
__device__ int   g_counts[N_EXP];
__device__ int   g_offsets[N_EXP];
__device__ int   g_tk_e[N_SLOT];
__device__ float g_tk_w[N_SLOT];
__device__ int   g_slot_tok2[N_SLOT];
__device__ float g_slot_w[N_SLOT];
__device__ int   g_tmap[NTILE_MAX];     // (e<<16)|mtile, -1 = none

// ---------------- helpers ----------------
__device__ __forceinline__ float gelu_exact(float v) {
    return 0.5f * v * (1.0f + erff(v * 0.70710678118654752f));
}
__device__ __forceinline__ uint32_t pack_h2(float lo, float hi) {
    uint32_t r; asm("cvt.rn.f16x2.f32 %0, %1, %2;" : "=r"(r) : "f"(hi), "f"(lo)); return r;
}
__device__ __forceinline__ uint2 pack_f4(float4 v) {
    return make_uint2(pack_h2(v.x, v.y), pack_h2(v.z, v.w));
}
__device__ __forceinline__ uint32_t smem_u32(const void* p) {
    uint32_t a;
    asm("{ .reg .u64 t; cvta.to.shared.u64 t, %1; cvt.u32.u64 %0, t; }" : "=r"(a) : "l"(p));
    return a;
}
__device__ __forceinline__ void cp_async16(uint32_t smem_dst, const void* gmem_src) {
    asm volatile("cp.async.cg.shared.global [%0], [%1], 16;\n" :: "r"(smem_dst), "l"(gmem_src));
}
__device__ __forceinline__ void cp_commit() { asm volatile("cp.async.commit_group;\n" ::: "memory"); }
template<int N>
__device__ __forceinline__ void cp_wait() { asm volatile("cp.async.wait_group %0;\n" :: "n"(N) : "memory"); }

__device__ __forceinline__ void ldsm_x4(uint32_t r[4], uint32_t addr) {
    asm volatile("ldmatrix.sync.aligned.m8n8.x4.shared.b16 {%0,%1,%2,%3}, [%4];"
                 : "=r"(r[0]), "=r"(r[1]), "=r"(r[2]), "=r"(r[3]) : "r"(addr));
}
__device__ __forceinline__ void ldsm_x4_t(uint32_t r[4], uint32_t addr) {
    asm volatile("ldmatrix.sync.aligned.m8n8.x4.trans.shared.b16 {%0,%1,%2,%3}, [%4];"
                 : "=r"(r[0]), "=r"(r[1]), "=r"(r[2]), "=r"(r[3]) : "r"(addr));
}
__device__ __forceinline__ void mma_f16(float c[4], const uint32_t a[4], const uint32_t b[2]) {
    asm volatile(
        "mma.sync.aligned.m16n8k16.row.col.f32.f16.f16.f32 "
        "{%0,%1,%2,%3}, {%4,%5,%6,%7}, {%8,%9}, {%0,%1,%2,%3};"
        : "+f"(c[0]), "+f"(c[1]), "+f"(c[2]), "+f"(c[3])
        : "r"(a[0]), "r"(a[1]), "r"(a[2]), "r"(a[3]), "r"(b[0]), "r"(b[1]));
}

// ---------------- router (+ fp16 conversion of x, + output zeroing) ----------------
__global__ void router_kernel(const float* __restrict__ x, const float* __restrict__ gw,
                              const float* __restrict__ gb, float* __restrict__ out,
                              float* __restrict__ logits_out) {
    int t = blockIdx.x, warp = threadIdx.x >> 5, lane = threadIdx.x & 31;
    const float* xr = x + (size_t)t * D_HID;
    float s = 0.0f;
    for (int i = lane; i < D_HID; i += 32) s += xr[i] * gw[i * N_EXP + warp];
#pragma unroll
    for (int o = 16; o; o >>= 1) s += __shfl_xor_sync(0xffffffffu, s, o);
    __shared__ float lg[N_EXP];
    if (lane == 0) lg[warp] = s + gb[warp];

    // fp16 conversion of this token's row + zero the output row (replaces memset)
    {
        const float4* x4 = (const float4*)xr;
        uint2* dst = (uint2*)(g_xh + (size_t)t * D_HID);
        float4* orow = (float4*)(out + (size_t)t * D_HID);
        const float4 z = make_float4(0.f, 0.f, 0.f, 0.f);
#pragma unroll
        for (int j = 0; j < 2; j++) {
            int i = threadIdx.x + j * 256;
            dst[i] = pack_f4(x4[i]);
            orow[i] = z;
        }
    }
    __syncthreads();

    if (threadIdx.x < N_EXP)
        logits_out[(size_t)t * N_EXP + threadIdx.x] = lg[threadIdx.x];

    if (threadIdx.x == 0) {
        float v0 = -1e30f, v1 = -1e30f; int e0 = 0, e1 = 0;
#pragma unroll
        for (int e = 0; e < N_EXP; e++) {
            float v = lg[e];
            if (v > v0)      { v1 = v0; e1 = e0; v0 = v; e0 = e; }
            else if (v > v1) { v1 = v;  e1 = e; }
        }
        float d = expf(v1 - v0), w1 = d / (1.0f + d), w0 = 1.0f - w1;
        g_tk_e[2*t] = e0;   g_tk_w[2*t] = w0;
        g_tk_e[2*t+1] = e1; g_tk_w[2*t+1] = w1;
    }
}

// ---------------- fused histogram + offsets + scatter + tile map ----------------
__global__ void scatter_kernel() {
    __shared__ int cnt[N_EXP], offs[N_EXP], cur[N_EXP];
    int tid = threadIdx.x;
    if (tid < N_EXP) cnt[tid] = 0;
    __syncthreads();
    int myE[4];
#pragma unroll
    for (int j = 0; j < 4; j++) {
        int i = tid + j * 1024;
        myE[j] = g_tk_e[i];
        atomicAdd(&cnt[myE[j]], 1);
    }
    __syncthreads();
    if (tid == 0) {
        int run = 0, nt = 0;
#pragma unroll
        for (int e = 0; e < N_EXP; e++) {
            offs[e] = run; cur[e] = run; run += cnt[e];
            int mt = (cnt[e] + 127) >> 7;       // tiles of 128 rows
            for (int m = 0; m < mt; m++) g_tmap[nt++] = (e << 16) | m;
        }
        for (; nt < NTILE_MAX; nt++) g_tmap[nt] = -1;
    }
    __syncthreads();
#pragma unroll
    for (int j = 0; j < 4; j++) {
        int i = tid + j * 1024;
        int pos = atomicAdd(&cur[myE[j]], 1);
        g_slot_tok2[pos] = i;
        g_slot_w[pos]    = g_tk_w[i];
    }
    if (tid < N_EXP) { g_counts[tid] = cnt[tid]; g_offsets[tid] = offs[tid]; }
}

// ---------------- GEMM config: BK=32, 3 stages (R11 proven) ----------------
#define STAGES 3
#define A_ROW  80               // bytes: 64B data + 16B pad
#define A_SZ   (128 * A_ROW)    // 10240 B

extern __shared__ char smem_c[];

// =======================================================================
// GEMM1: 128x64x32 dual-B. h = gelu(x@Wu) * (x@Wg + 1)
//   warps 4x2; warp tile 32x32 per matrix
// =======================================================================
#define B1_ROW 144
#define B1_SZ  (32 * B1_ROW)
#define G1_STG (A_SZ + 2 * B1_SZ)
#define G1_SMEM (STAGES * G1_STG)

__global__ void __launch_bounds__(256, 2)
gemm1_kernel(const float* __restrict__ w_up, const float* __restrict__ w_gate) {
    int tmv = g_tmap[blockIdx.y];
    if (tmv < 0) return;
    int e = tmv >> 16, m0 = (tmv & 0xffff) * 128;
    int cnt = g_counts[e];
    int n0 = blockIdx.x * 64;
    int off = g_offsets[e];
    const float* Wu = w_up   + (size_t)e * D_HID * N_INT;
    const float* Wg = w_gate + (size_t)e * D_HID * N_INT;

    char* smem = smem_c;
    uint32_t sbase = smem_u32(smem_c);

    int tid = threadIdx.x;
    int warp = tid >> 5, lane = tid & 31;
    int wm = warp >> 1, wn = warp & 1;
    int grp = lane >> 2, qid = lane & 3;

    int rA = tid >> 2, qA = tid & 3;
    const __half* aptr[2];
#pragma unroll
    for (int i = 0; i < 2; i++) {
        int gm = m0 + rA + 64*i;
        int slot = (gm < cnt) ? (off + gm) : off;
        int tok = g_slot_tok2[slot] >> 1;
        aptr[i] = g_xh + (size_t)tok * D_HID + qA * 8;
    }
    int kB = tid >> 4, nqB = tid & 15;
    const float* pu = Wu + (size_t)kB * N_INT + n0 + nqB*4;
    const float* pg = Wg + (size_t)kB * N_INT + n0 + nqB*4;

    int lr = lane & 7, ls = lane >> 3;
    uint32_t aOff = (wm*32 + (ls & 1)*8 + lr) * A_ROW + (ls >> 1) * 16;
    uint32_t bOff = ((ls & 1)*8 + lr) * B1_ROW + (wn*32)*2 + (ls >> 1)*16;

    float accU[2][4][4], accG[2][4][4];
#pragma unroll
    for (int a = 0; a < 2; a++)
#pragma unroll
        for (int b = 0; b < 4; b++)
#pragma unroll
            for (int c = 0; c < 4; c++) { accU[a][b][c] = 0.f; accG[a][b][c] = 0.f; }

    const int KT = D_HID / 32;   // 64
    float4 rbu[2], rbg[2];

    auto prefetchB = [&](int kt) {
        size_t ko = (size_t)kt * 32 * N_INT;
#pragma unroll
        for (int i = 0; i < 2; i++) {
            rbu[i] = *(const float4*)(pu + ko + (size_t)(16*i) * N_INT);
            rbg[i] = *(const float4*)(pg + ko + (size_t)(16*i) * N_INT);
        }
    };
    auto fill = [&](int kt) {
        int s = kt % STAGES;
        char* sb = smem + s*G1_STG + A_SZ;
#pragma unroll
        for (int i = 0; i < 2; i++) {
            uint32_t so = (kB + 16*i)*B1_ROW + nqB*8;
            *(uint2*)(sb + so)         = pack_f4(rbu[i]);
            *(uint2*)(sb + B1_SZ + so) = pack_f4(rbg[i]);
        }
        uint32_t sa = sbase + s*G1_STG;
#pragma unroll
        for (int i = 0; i < 2; i++)
            cp_async16(sa + (rA + 64*i)*A_ROW + qA*16, aptr[i] + kt*32);
        cp_commit();
    };

    prefetchB(0); fill(0);
    prefetchB(1); fill(1);
    prefetchB(2);

    for (int kt = 0; kt < KT; kt++) {
        cp_wait<1>();
        __syncthreads();

        if (kt + 2 < KT) {
            fill(kt + 2);
            if (kt + 3 < KT) prefetchB(kt + 3);
        } else cp_commit();

        int s = kt % STAGES;
        uint32_t aB = sbase + s*G1_STG + aOff;
        uint32_t bB = sbase + s*G1_STG + A_SZ + bOff;
#pragma unroll
        for (int ks = 0; ks < 2; ks++) {
            uint32_t a[2][4];
#pragma unroll
            for (int fm = 0; fm < 2; fm++) ldsm_x4(a[fm], aB + fm*(16*A_ROW) + ks*32);
            uint32_t bu[2][4], bg[2][4];
#pragma unroll
            for (int p = 0; p < 2; p++) {
                ldsm_x4_t(bu[p], bB + p*32 + ks*(16*B1_ROW));
                ldsm_x4_t(bg[p], bB + B1_SZ + p*32 + ks*(16*B1_ROW));
            }
#pragma unroll
            for (int fm = 0; fm < 2; fm++)
#pragma unroll
                for (int p = 0; p < 2; p++) {
                    mma_f16(accU[fm][2*p],   a[fm], &bu[p][0]);
                    mma_f16(accU[fm][2*p+1], a[fm], &bu[p][2]);
                    mma_f16(accG[fm][2*p],   a[fm], &bg[p][0]);
                    mma_f16(accG[fm][2*p+1], a[fm], &bg[p][2]);
                }
        }
    }

#pragma unroll
    for (int fm = 0; fm < 2; fm++) {
        int r0 = wm*32 + fm*16 + grp;
#pragma unroll
        for (int half_ = 0; half_ < 2; half_++) {
            int gm = m0 + r0 + half_*8;
            if (gm < cnt) {
                __half* hrow = g_h + (size_t)(off + gm) * N_INT + n0;
#pragma unroll
                for (int fn = 0; fn < 4; fn++) {
                    int c = wn*32 + fn*8 + qid*2;
                    float u0 = accU[fm][fn][half_*2+0], u1 = accU[fm][fn][half_*2+1];
                    float g0 = accG[fm][fn][half_*2+0], g1 = accG[fm][fn][half_*2+1];
                    float h0 = gelu_exact(u0) * (g0 + 1.0f);
                    float h1 = gelu_exact(u1) * (g1 + 1.0f);
                    *(uint32_t*)(hrow + c) = pack_h2(h0, h1);
                }
            }
        }
    }
}

// =======================================================================
// GEMM2: 128x128x32. out[t] += w * (h @ Wd)  (atomicAdd, 2 contributions)
//   warps 4x2; warp tile 32x64
// =======================================================================
#define B2_ROW 272
#define B2_SZ  (32 * B2_ROW)
#define G2_STG (A_SZ + B2_SZ)
#define G2_SMEM (STAGES * G2_STG)

__global__ void __launch_bounds__(256, 2)
gemm2_kernel(const float* __restrict__ w_down, float* __restrict__ out) {
    int tmv = g_tmap[blockIdx.y];
    if (tmv < 0) return;
    int e = tmv >> 16, m0 = (tmv & 0xffff) * 128;
    int cnt = g_counts[e];
    int n0 = blockIdx.x * 128;
    int off = g_offsets[e];
    const float* Wd = w_down + (size_t)e * N_INT * D_HID;

    char* smem = smem_c;
    uint32_t sbase = smem_u32(smem_c);

    int tid = threadIdx.x;
    int warp = tid >> 5, lane = tid & 31;
    int wm = warp >> 1, wn = warp & 1;
    int grp = lane >> 2, qid = lane & 3;

    int rA = tid >> 2, qA = tid & 3;
    const __half* aptr[2];
#pragma unroll
    for (int i = 0; i < 2; i++) {
        int gm = m0 + rA + 64*i;
        int slot = (gm < cnt) ? (off + gm) : off;
        aptr[i] = g_h + (size_t)slot * N_INT + qA * 8;
    }
    int kB = tid >> 5, nqB = tid & 31;
    const float* pd = Wd + (size_t)kB * D_HID + n0 + nqB*4;

    int lr = lane & 7, ls = lane >> 3;
    uint32_t aOff = (wm*32 + (ls & 1)*8 + lr) * A_ROW + (ls >> 1) * 16;
    uint32_t bOff = ((ls & 1)*8 + lr) * B2_ROW + (wn*64)*2 + (ls >> 1)*16;

    float acc[2][8][4];
#pragma unroll
    for (int a = 0; a < 2; a++)
#pragma unroll
        for (int b = 0; b < 8; b++)
#pragma unroll
            for (int c = 0; c < 4; c++) acc[a][b][c] = 0.f;

    const int KT = N_INT / 32;   // 32
    float4 rb[4];

    auto prefetchB = [&](int kt) {
        size_t ko = (size_t)kt * 32 * D_HID;
#pragma unroll
        for (int i = 0; i < 4; i++)
            rb[i] = *(const float4*)(pd + ko + (size_t)(8*i) * D_HID);
    };
    auto fill = [&](int kt) {
        int s = kt % STAGES;
        char* sb = smem + s*G2_STG + A_SZ;
#pragma unroll
        for (int i = 0; i < 4; i++)
            *(uint2*)(sb + (kB + 8*i)*B2_ROW + nqB*8) = pack_f4(rb[i]);
        uint32_t sa = sbase + s*G2_STG;
#pragma unroll
        for (int i = 0; i < 2; i++)
            cp_async16(sa + (rA + 64*i)*A_ROW + qA*16, aptr[i] + kt*32);
        cp_commit();
    };

    prefetchB(0); fill(0);
    prefetchB(1); fill(1);
    prefetchB(2);

    for (int kt = 0; kt < KT; kt++) {
        cp_wait<1>();
        __syncthreads();

        if (kt + 2 < KT) {
            fill(kt + 2);
            if (kt + 3 < KT) prefetchB(kt + 3);
        } else cp_commit();

        int s = kt % STAGES;
        uint32_t aB = sbase + s*G2_STG + aOff;
        uint32_t bB = sbase + s*G2_STG + A_SZ + bOff;
#pragma unroll
        for (int ks = 0; ks < 2; ks++) {
            uint32_t a[2][4];
#pragma unroll
            for (int fm = 0; fm < 2; fm++) ldsm_x4(a[fm], aB + fm*(16*A_ROW) + ks*32);
            uint32_t b[4][4];
#pragma unroll
            for (int p = 0; p < 4; p++)
                ldsm_x4_t(b[p], bB + p*32 + ks*(16*B2_ROW));
#pragma unroll
            for (int fm = 0; fm < 2; fm++)
#pragma unroll
                for (int p = 0; p < 4; p++) {
                    mma_f16(acc[fm][2*p],   a[fm], &b[p][0]);
                    mma_f16(acc[fm][2*p+1], a[fm], &b[p][2]);
                }
        }
    }

    // epilogue: out[tok] += w * acc (exactly 2 adds/element -> deterministic)
#pragma unroll
    for (int fm = 0; fm < 2; fm++) {
        int r0 = wm*32 + fm*16 + grp;
#pragma unroll
        for (int half_ = 0; half_ < 2; half_++) {
            int gm = m0 + r0 + half_*8;
            if (gm < cnt) {
                int slot = off + gm;
                int tok = g_slot_tok2[slot] >> 1;
                float wv = g_slot_w[slot];
                float* orow = out + (size_t)tok * D_HID + n0;
#pragma unroll
                for (int fn = 0; fn < 8; fn++) {
                    int c = wn*64 + fn*8 + qid*2;
                    atomicAdd(orow + c,     wv * acc[fm][fn][half_*2+0]);
                    atomicAdd(orow + c + 1, wv * acc[fm][fn][half_*2+1]);
                }
            }
        }
    }
}

// ---------------- launch ----------------
extern "C" void kernel_launch(void* const* d_in, const int* in_sizes, int n_in,
                              void* d_out, int out_size) {
    const float* x  = (const float*)d_in[0];
    const float* gw = (const float*)d_in[1];
    const float* gb = (const float*)d_in[2];
    const float* wu = (const float*)d_in[3];
    const float* wg = (const float*)d_in[4];
    const float* wd = (const float*)d_in[5];

    float* out    = (float*)d_out;
    float* logits = out + (out_size - T_TOK * N_EXP);

    cudaFuncSetAttribute(gemm1_kernel, cudaFuncAttributeMaxDynamicSharedMemorySize, G1_SMEM);
    cudaFuncSetAttribute(gemm2_kernel, cudaFuncAttributeMaxDynamicSharedMemorySize, G2_SMEM);

    router_kernel<<<T_TOK, 256>>>(x, gw, gb, out, logits);
    scatter_kernel<<<1, 1024>>>();

    dim3 g1(N_INT / 64, NTILE_MAX, 1);     // (16, 40)
    gemm1_kernel<<<g1, 256, G1_SMEM>>>(wu, wg);

    dim3 g2(D_HID / 128, NTILE_MAX, 1);    // (16, 40)
    gemm2_kernel<<<g2, 256, G2_SMEM>>>(wd, out);
}

// round 15
// speedup vs baseline: 1.6900x; 1.0079x over previous
#include <cuda_runtime.h>
#include <cuda_fp16.h>
#include <math.h>
#include <stdint.h>

#define T_TOK 2048
#define D_HID 2048
#define N_INT 1024
#define N_EXP 8
#define N_SLOT (T_TOK*2)
#define NTILE_MAX 40            // sum ceil(cnt_e/128) <= 40

// ---------------- scratch ----------------
__device__ __align__(256) __half g_xh[(size_t)T_TOK * D_HID];   // fp16 x (router writes)
__device__ __align__(256) __half g_h[(size_t)N_SLOT * N_INT];   // fp16 intermediate
__device__ int   g_counts[N_EXP];
__device__ int   g_offsets[N_EXP];
__device__ int   g_tk_e[N_SLOT];
__device__ float g_tk_w[N_SLOT];
__device__ int   g_slot_tok2[N_SLOT];
__device__ float g_slot_w[N_SLOT];
__device__ int   g_tmap[NTILE_MAX];     // (e<<16)|mtile, -1 = none

// ---------------- helpers ----------------
__device__ __forceinline__ float gelu_exact(float v) {
    return 0.5f * v * (1.0f + erff(v * 0.70710678118654752f));
}
__device__ __forceinline__ uint32_t pack_h2(float lo, float hi) {
    uint32_t r; asm("cvt.rn.f16x2.f32 %0, %1, %2;" : "=r"(r) : "f"(hi), "f"(lo)); return r;
}
__device__ __forceinline__ uint2 pack_f4(float4 v) {
    return make_uint2(pack_h2(v.x, v.y), pack_h2(v.z, v.w));
}
__device__ __forceinline__ uint32_t smem_u32(const void* p) {
    uint32_t a;
    asm("{ .reg .u64 t; cvta.to.shared.u64 t, %1; cvt.u32.u64 %0, t; }" : "=r"(a) : "l"(p));
    return a;
}
__device__ __forceinline__ void cp_async16(uint32_t smem_dst, const void* gmem_src) {
    asm volatile("cp.async.cg.shared.global [%0], [%1], 16;\n" :: "r"(smem_dst), "l"(gmem_src));
}
__device__ __forceinline__ void cp_commit() { asm volatile("cp.async.commit_group;\n" ::: "memory"); }
template<int N>
__device__ __forceinline__ void cp_wait() { asm volatile("cp.async.wait_group %0;\n" :: "n"(N) : "memory"); }

__device__ __forceinline__ void ldsm_x4(uint32_t r[4], uint32_t addr) {
    asm volatile("ldmatrix.sync.aligned.m8n8.x4.shared.b16 {%0,%1,%2,%3}, [%4];"
                 : "=r"(r[0]), "=r"(r[1]), "=r"(r[2]), "=r"(r[3]) : "r"(addr));
}
__device__ __forceinline__ void ldsm_x4_t(uint32_t r[4], uint32_t addr) {
    asm volatile("ldmatrix.sync.aligned.m8n8.x4.trans.shared.b16 {%0,%1,%2,%3}, [%4];"
                 : "=r"(r[0]), "=r"(r[1]), "=r"(r[2]), "=r"(r[3]) : "r"(addr));
}
__device__ __forceinline__ void mma_f16(float c[4], const uint32_t a[4], const uint32_t b[2]) {
    asm volatile(
        "mma.sync.aligned.m16n8k16.row.col.f32.f16.f16.f32 "
        "{%0,%1,%2,%3}, {%4,%5,%6,%7}, {%8,%9}, {%0,%1,%2,%3};"
        : "+f"(c[0]), "+f"(c[1]), "+f"(c[2]), "+f"(c[3])
        : "r"(a[0]), "r"(a[1]), "r"(a[2]), "r"(a[3]), "r"(b[0]), "r"(b[1]));
}

// ---------------- router: coalesced 8-acc dot + fp16 convert + out zeroing ----------------
__global__ void router_kernel(const float* __restrict__ x, const float* __restrict__ gw,
                              const float* __restrict__ gb, float* __restrict__ out,
                              float* __restrict__ logits_out) {
    int t = blockIdx.x;
    int tid = threadIdx.x;
    int lane = tid & 31, warp = tid >> 5;
    const float* xr = x + (size_t)t * D_HID;

    // Each thread owns 8 consecutive x floats: [tid*8, tid*8+8).
    // gw slab for them: gw[tid*8*8 .. +64) = 256B contiguous (coalesced).
    float acc[N_EXP];
#pragma unroll
    for (int e = 0; e < N_EXP; e++) acc[e] = 0.f;

    {
        const float4* x4 = (const float4*)xr;
        const float4* g4 = (const float4*)(gw + (size_t)tid * 8 * N_EXP);
        uint2* dst = (uint2*)(g_xh + (size_t)t * D_HID);
        float4* orow = (float4*)(out + (size_t)t * D_HID);
        const float4 z = make_float4(0.f, 0.f, 0.f, 0.f);
#pragma unroll
        for (int j = 0; j < 2; j++) {          // two float4 of x per thread
            float4 v = x4[tid * 2 + j];
            dst[tid * 2 + j] = pack_f4(v);     // fp16 conversion
            orow[tid * 2 + j] = z;             // zero output row (replaces memset)
            float xv[4] = {v.x, v.y, v.z, v.w};
#pragma unroll
            for (int k = 0; k < 4; k++) {      // x element idx = j*4+k
                float4 ga = g4[(j * 4 + k) * 2];
                float4 gb4 = g4[(j * 4 + k) * 2 + 1];
                acc[0] += xv[k] * ga.x;  acc[1] += xv[k] * ga.y;
                acc[2] += xv[k] * ga.z;  acc[3] += xv[k] * ga.w;
                acc[4] += xv[k] * gb4.x; acc[5] += xv[k] * gb4.y;
                acc[6] += xv[k] * gb4.z; acc[7] += xv[k] * gb4.w;
            }
        }
    }

    // warp reduce all 8 accs
#pragma unroll
    for (int o = 16; o; o >>= 1)
#pragma unroll
        for (int e = 0; e < N_EXP; e++)
            acc[e] += __shfl_xor_sync(0xffffffffu, acc[e], o);

    __shared__ float part[8][N_EXP];
    if (lane == 0)
#pragma unroll
        for (int e = 0; e < N_EXP; e++) part[warp][e] = acc[e];
    __syncthreads();

    __shared__ float lg[N_EXP];
    if (tid < N_EXP) {
        float s = gb[tid];
#pragma unroll
        for (int w = 0; w < 8; w++) s += part[w][tid];
        lg[tid] = s;
        logits_out[(size_t)t * N_EXP + tid] = s;
    }
    __syncthreads();

    if (tid == 0) {
        float v0 = -1e30f, v1 = -1e30f; int e0 = 0, e1 = 0;
#pragma unroll
        for (int e = 0; e < N_EXP; e++) {
            float v = lg[e];
            if (v > v0)      { v1 = v0; e1 = e0; v0 = v; e0 = e; }
            else if (v > v1) { v1 = v;  e1 = e; }
        }
        float d = expf(v1 - v0), w1 = d / (1.0f + d), w0 = 1.0f - w1;
        g_tk_e[2*t] = e0;   g_tk_w[2*t] = w0;
        g_tk_e[2*t+1] = e1; g_tk_w[2*t+1] = w1;
    }
}

// ---------------- fused histogram + offsets + scatter + tile map ----------------
__global__ void scatter_kernel() {
    __shared__ int cnt[N_EXP], offs[N_EXP], cur[N_EXP];
    int tid = threadIdx.x;
    if (tid < N_EXP) cnt[tid] = 0;
    __syncthreads();
    int myE[4];
#pragma unroll
    for (int j = 0; j < 4; j++) {
        int i = tid + j * 1024;
        myE[j] = g_tk_e[i];
        atomicAdd(&cnt[myE[j]], 1);
    }
    __syncthreads();
    if (tid == 0) {
        int run = 0, nt = 0;
#pragma unroll
        for (int e = 0; e < N_EXP; e++) {
            offs[e] = run; cur[e] = run; run += cnt[e];
            int mt = (cnt[e] + 127) >> 7;       // tiles of 128 rows
            for (int m = 0; m < mt; m++) g_tmap[nt++] = (e << 16) | m;
        }
        for (; nt < NTILE_MAX; nt++) g_tmap[nt] = -1;
    }
    __syncthreads();
#pragma unroll
    for (int j = 0; j < 4; j++) {
        int i = tid + j * 1024;
        int pos = atomicAdd(&cur[myE[j]], 1);
        g_slot_tok2[pos] = i;
        g_slot_w[pos]    = g_tk_w[i];
    }
    if (tid < N_EXP) { g_counts[tid] = cnt[tid]; g_offsets[tid] = offs[tid]; }
}

// ---------------- GEMM config: BK=32, 3 stages (R11/R14 proven) ----------------
#define STAGES 3
#define A_ROW  80               // bytes: 64B data + 16B pad
#define A_SZ   (128 * A_ROW)    // 10240 B

extern __shared__ char smem_c[];

// =======================================================================
// GEMM1: 128x64x32 dual-B. h = gelu(x@Wu) * (x@Wg + 1)
//   warps 4x2; warp tile 32x32 per matrix
// =======================================================================
#define B1_ROW 144
#define B1_SZ  (32 * B1_ROW)
#define G1_STG (A_SZ + 2 * B1_SZ)
#define G1_SMEM (STAGES * G1_STG)

__global__ void __launch_bounds__(256, 2)
gemm1_kernel(const float* __restrict__ w_up, const float* __restrict__ w_gate) {
    int tmv = g_tmap[blockIdx.y];
    if (tmv < 0) return;
    int e = tmv >> 16, m0 = (tmv & 0xffff) * 128;
    int cnt = g_counts[e];
    int n0 = blockIdx.x * 64;
    int off = g_offsets[e];
    const float* Wu = w_up   + (size_t)e * D_HID * N_INT;
    const float* Wg = w_gate + (size_t)e * D_HID * N_INT;

    char* smem = smem_c;
    uint32_t sbase = smem_u32(smem_c);

    int tid = threadIdx.x;
    int warp = tid >> 5, lane = tid & 31;
    int wm = warp >> 1, wn = warp & 1;
    int grp = lane >> 2, qid = lane & 3;

    int rA = tid >> 2, qA = tid & 3;
    const __half* aptr[2];
#pragma unroll
    for (int i = 0; i < 2; i++) {
        int gm = m0 + rA + 64*i;
        int slot = (gm < cnt) ? (off + gm) : off;
        int tok = g_slot_tok2[slot] >> 1;
        aptr[i] = g_xh + (size_t)tok * D_HID + qA * 8;
    }
    int kB = tid >> 4, nqB = tid & 15;
    const float* pu = Wu + (size_t)kB * N_INT + n0 + nqB*4;
    const float* pg = Wg + (size_t)kB * N_INT + n0 + nqB*4;

    int lr = lane & 7, ls = lane >> 3;
    uint32_t aOff = (wm*32 + (ls & 1)*8 + lr) * A_ROW + (ls >> 1) * 16;
    uint32_t bOff = ((ls & 1)*8 + lr) * B1_ROW + (wn*32)*2 + (ls >> 1)*16;

    float accU[2][4][4], accG[2][4][4];
#pragma unroll
    for (int a = 0; a < 2; a++)
#pragma unroll
        for (int b = 0; b < 4; b++)
#pragma unroll
            for (int c = 0; c < 4; c++) { accU[a][b][c] = 0.f; accG[a][b][c] = 0.f; }

    const int KT = D_HID / 32;   // 64
    float4 rbu[2], rbg[2];

    auto prefetchB = [&](int kt) {
        size_t ko = (size_t)kt * 32 * N_INT;
#pragma unroll
        for (int i = 0; i < 2; i++) {
            rbu[i] = *(const float4*)(pu + ko + (size_t)(16*i) * N_INT);
            rbg[i] = *(const float4*)(pg + ko + (size_t)(16*i) * N_INT);
        }
    };
    auto fill = [&](int kt) {
        int s = kt % STAGES;
        char* sb = smem + s*G1_STG + A_SZ;
#pragma unroll
        for (int i = 0; i < 2; i++) {
            uint32_t so = (kB + 16*i)*B1_ROW + nqB*8;
            *(uint2*)(sb + so)         = pack_f4(rbu[i]);
            *(uint2*)(sb + B1_SZ + so) = pack_f4(rbg[i]);
        }
        uint32_t sa = sbase + s*G1_STG;
#pragma unroll
        for (int i = 0; i < 2; i++)
            cp_async16(sa + (rA + 64*i)*A_ROW + qA*16, aptr[i] + kt*32);
        cp_commit();
    };

    prefetchB(0); fill(0);
    prefetchB(1); fill(1);
    prefetchB(2);

    for (int kt = 0; kt < KT; kt++) {
        cp_wait<1>();
        __syncthreads();

        if (kt + 2 < KT) {
            fill(kt + 2);
            if (kt + 3 < KT) prefetchB(kt + 3);
        } else cp_commit();

        int s = kt % STAGES;
        uint32_t aB = sbase + s*G1_STG + aOff;
        uint32_t bB = sbase + s*G1_STG + A_SZ + bOff;
#pragma unroll
        for (int ks = 0; ks < 2; ks++) {
            uint32_t a[2][4];
#pragma unroll
            for (int fm = 0; fm < 2; fm++) ldsm_x4(a[fm], aB + fm*(16*A_ROW) + ks*32);
            uint32_t bu[2][4], bg[2][4];
#pragma unroll
            for (int p = 0; p < 2; p++) {
                ldsm_x4_t(bu[p], bB + p*32 + ks*(16*B1_ROW));
                ldsm_x4_t(bg[p], bB + B1_SZ + p*32 + ks*(16*B1_ROW));
            }
#pragma unroll
            for (int fm = 0; fm < 2; fm++)
#pragma unroll
                for (int p = 0; p < 2; p++) {
                    mma_f16(accU[fm][2*p],   a[fm], &bu[p][0]);
                    mma_f16(accU[fm][2*p+1], a[fm], &bu[p][2]);
                    mma_f16(accG[fm][2*p],   a[fm], &bg[p][0]);
                    mma_f16(accG[fm][2*p+1], a[fm], &bg[p][2]);
                }
        }
    }

#pragma unroll
    for (int fm = 0; fm < 2; fm++) {
        int r0 = wm*32 + fm*16 + grp;
#pragma unroll
        for (int half_ = 0; half_ < 2; half_++) {
            int gm = m0 + r0 + half_*8;
            if (gm < cnt) {
                __half* hrow = g_h + (size_t)(off + gm) * N_INT + n0;
#pragma unroll
                for (int fn = 0; fn < 4; fn++) {
                    int c = wn*32 + fn*8 + qid*2;
                    float u0 = accU[fm][fn][half_*2+0], u1 = accU[fm][fn][half_*2+1];
                    float g0 = accG[fm][fn][half_*2+0], g1 = accG[fm][fn][half_*2+1];
                    float h0 = gelu_exact(u0) * (g0 + 1.0f);
                    float h1 = gelu_exact(u1) * (g1 + 1.0f);
                    *(uint32_t*)(hrow + c) = pack_h2(h0, h1);
                }
            }
        }
    }
}

// =======================================================================
// GEMM2: 128x128x32. out[t] += w * (h @ Wd)  (atomicAdd, 2 contributions)
//   warps 4x2; warp tile 32x64
// =======================================================================
#define B2_ROW 272
#define B2_SZ  (32 * B2_ROW)
#define G2_STG (A_SZ + B2_SZ)
#define G2_SMEM (STAGES * G2_STG)

__global__ void __launch_bounds__(256, 2)
gemm2_kernel(const float* __restrict__ w_down, float* __restrict__ out) {
    int tmv = g_tmap[blockIdx.y];
    if (tmv < 0) return;
    int e = tmv >> 16, m0 = (tmv & 0xffff) * 128;
    int cnt = g_counts[e];
    int n0 = blockIdx.x * 128;
    int off = g_offsets[e];
    const float* Wd = w_down + (size_t)e * N_INT * D_HID;

    char* smem = smem_c;
    uint32_t sbase = smem_u32(smem_c);

    int tid = threadIdx.x;
    int warp = tid >> 5, lane = tid & 31;
    int wm = warp >> 1, wn = warp & 1;
    int grp = lane >> 2, qid = lane & 3;

    int rA = tid >> 2, qA = tid & 3;
    const __half* aptr[2];
#pragma unroll
    for (int i = 0; i < 2; i++) {
        int gm = m0 + rA + 64*i;
        int slot = (gm < cnt) ? (off + gm) : off;
        aptr[i] = g_h + (size_t)slot * N_INT + qA * 8;
    }
    int kB = tid >> 5, nqB = tid & 31;
    const float* pd = Wd + (size_t)kB * D_HID + n0 + nqB*4;

    int lr = lane & 7, ls = lane >> 3;
    uint32_t aOff = (wm*32 + (ls & 1)*8 + lr) * A_ROW + (ls >> 1) * 16;
    uint32_t bOff = ((ls & 1)*8 + lr) * B2_ROW + (wn*64)*2 + (ls >> 1)*16;

    float acc[2][8][4];
#pragma unroll
    for (int a = 0; a < 2; a++)
#pragma unroll
        for (int b = 0; b < 8; b++)
#pragma unroll
            for (int c = 0; c < 4; c++) acc[a][b][c] = 0.f;

    const int KT = N_INT / 32;   // 32
    float4 rb[4];

    auto prefetchB = [&](int kt) {
        size_t ko = (size_t)kt * 32 * D_HID;
#pragma unroll
        for (int i = 0; i < 4; i++)
            rb[i] = *(const float4*)(pd + ko + (size_t)(8*i) * D_HID);
    };
    auto fill = [&](int kt) {
        int s = kt % STAGES;
        char* sb = smem + s*G2_STG + A_SZ;
#pragma unroll
        for (int i = 0; i < 4; i++)
            *(uint2*)(sb + (kB + 8*i)*B2_ROW + nqB*8) = pack_f4(rb[i]);
        uint32_t sa = sbase + s*G2_STG;
#pragma unroll
        for (int i = 0; i < 2; i++)
            cp_async16(sa + (rA + 64*i)*A_ROW + qA*16, aptr[i] + kt*32);
        cp_commit();
    };

    prefetchB(0); fill(0);
    prefetchB(1); fill(1);
    prefetchB(2);

    for (int kt = 0; kt < KT; kt++) {
        cp_wait<1>();
        __syncthreads();

        if (kt + 2 < KT) {
            fill(kt + 2);
            if (kt + 3 < KT) prefetchB(kt + 3);
        } else cp_commit();

        int s = kt % STAGES;
        uint32_t aB = sbase + s*G2_STG + aOff;
        uint32_t bB = sbase + s*G2_STG + A_SZ + bOff;
#pragma unroll
        for (int ks = 0; ks < 2; ks++) {
            uint32_t a[2][4];
#pragma unroll
            for (int fm = 0; fm < 2; fm++) ldsm_x4(a[fm], aB + fm*(16*A_ROW) + ks*32);
            uint32_t b[4][4];
#pragma unroll
            for (int p = 0; p < 4; p++)
                ldsm_x4_t(b[p], bB + p*32 + ks*(16*B2_ROW));
#pragma unroll
            for (int fm = 0; fm < 2; fm++)
#pragma unroll
                for (int p = 0; p < 4; p++) {
                    mma_f16(acc[fm][2*p],   a[fm], &b[p][0]);
                    mma_f16(acc[fm][2*p+1], a[fm], &b[p][2]);
                }
        }
    }

    // epilogue: out[tok] += w * acc (exactly 2 adds/element -> deterministic)
#pragma unroll
    for (int fm = 0; fm < 2; fm++) {
        int r0 = wm*32 + fm*16 + grp;
#pragma unroll
        for (int half_ = 0; half_ < 2; half_++) {
            int gm = m0 + r0 + half_*8;
            if (gm < cnt) {
                int slot = off + gm;
                int tok = g_slot_tok2[slot] >> 1;
                float wv = g_slot_w[slot];
                float* orow = out + (size_t)tok * D_HID + n0;
#pragma unroll
                for (int fn = 0; fn < 8; fn++) {
                    int c = wn*64 + fn*8 + qid*2;
                    atomicAdd(orow + c,     wv * acc[fm][fn][half_*2+0]);
                    atomicAdd(orow + c + 1, wv * acc[fm][fn][half_*2+1]);
                }
            }
        }
    }
}

// ---------------- launch ----------------
extern "C" void kernel_launch(void* const* d_in, const int* in_sizes, int n_in,
                              void* d_out, int out_size) {
    const float* x  = (const float*)d_in[0];
    const float* gw = (const float*)d_in[1];
    const float* gb = (const float*)d_in[2];
    const float* wu = (const float*)d_in[3];
    const float* wg = (const float*)d_in[4];
    const float* wd = (const float*)d_in[5];

    float* out    = (float*)d_out;
    float* logits = out + (out_size - T_TOK * N_EXP);

    cudaFuncSetAttribute(gemm1_kernel, cudaFuncAttributeMaxDynamicSharedMemorySize, G1_SMEM);
    cudaFuncSetAttribute(gemm2_kernel, cudaFuncAttributeMaxDynamicSharedMemorySize, G2_SMEM);

    router_kernel<<<T_TOK, 256>>>(x, gw, gb, out, logits);
    scatter_kernel<<<1, 1024>>>();

    dim3 g1(N_INT / 64, NTILE_MAX, 1);     // (16, 40)
    gemm1_kernel<<<g1, 256, G1_SMEM>>>(wu, wg);

    dim3 g2(D_HID / 128, NTILE_MAX, 1);    // (16, 40)
    gemm2_kernel<<<g2, 256, G2_SMEM>>>(wd, out);
}